// round 10
// baseline (speedup 1.0000x reference)
#include <cuda_runtime.h>

#define NODES 50000
#define NEDGES 800000
#define F 128

// ---------------- scratch (device globals; no runtime allocation) ------------
__device__ int   g_cnt[NODES];
__device__ int   g_off[NODES + 1];
__device__ int   g_cur[NODES];
__device__ int   g_csr[NEDGES];
__device__ int   g_part[64];
__device__ float g_h1[NODES * F];
__device__ int   g_is64;

// ---------------- index dtype detection --------------------------------------
__global__ void detect_kernel(const int* __restrict__ p) {
    __shared__ int ok;
    if (threadIdx.x == 0) ok = 1;
    __syncthreads();
    if (p[2 * threadIdx.x + 1] != 0) atomicAnd(&ok, 0);
    __syncthreads();
    if (threadIdx.x == 0) g_is64 = ok;
}

__device__ __forceinline__ int load_idx(const void* __restrict__ p, long i, int is64) {
    if (is64) return (int)((const long long*)p)[i];
    return ((const int*)p)[i];
}

// ---------------- zero fill (two arrays in one launch) ------------------------
__global__ void zero2_kernel(int* __restrict__ a, int* __restrict__ b, int n4) {
    int i = blockIdx.x * blockDim.x + threadIdx.x;
    int4 z = make_int4(0, 0, 0, 0);
    for (; i < n4; i += gridDim.x * blockDim.x) {
        ((int4*)a)[i] = z;
        ((int4*)b)[i] = z;
    }
}

// ---------------- CSR build --------------------------------------------------
__global__ void count_kernel(const void* __restrict__ ei, int* __restrict__ cnt, int nE) {
    int i = blockIdx.x * blockDim.x + threadIdx.x;
    int is64 = g_is64;
    if (i < nE) {
        int d = load_idx(ei, (long)nE + i, is64);
        if ((unsigned)d < NODES) atomicAdd(&cnt[d], 1);
    }
}

__global__ __launch_bounds__(1024) void scan1_kernel(
    const int* __restrict__ cnt, int* __restrict__ off, int* __restrict__ part, int n)
{
    __shared__ int wsum[32];
    int tid = threadIdx.x, lane = tid & 31, wid = tid >> 5;
    int g = blockIdx.x * 1024 + tid;
    int v = (g < n) ? cnt[g] : 0;
    int s = v;
#pragma unroll
    for (int d = 1; d < 32; d <<= 1) {
        int t = __shfl_up_sync(0xffffffffu, s, d);
        if (lane >= d) s += t;
    }
    if (lane == 31) wsum[wid] = s;
    __syncthreads();
    if (wid == 0) {
        int ws = wsum[lane];
#pragma unroll
        for (int d = 1; d < 32; d <<= 1) {
            int t = __shfl_up_sync(0xffffffffu, ws, d);
            if (lane >= d) ws += t;
        }
        wsum[lane] = ws;
    }
    __syncthreads();
    int base = wid ? wsum[wid - 1] : 0;
    if (g < n) off[g] = base + s - v;
    if (tid == 1023) part[blockIdx.x] = wsum[31];
}

__global__ void scan2_kernel(int* __restrict__ part, int nb) {
    if (threadIdx.x == 0) {
        int run = 0;
        for (int i = 0; i < nb; i++) { int t = part[i]; part[i] = run; run += t; }
        part[nb] = run;
    }
}

__global__ __launch_bounds__(1024) void scan3_kernel(
    int* __restrict__ off, const int* __restrict__ part, int n, int nb)
{
    int g = blockIdx.x * 1024 + threadIdx.x;
    if (g < n) off[g] += part[blockIdx.x];
    if (g == 0) off[n] = part[nb];
}

__global__ void fill_kernel(const void* __restrict__ ei,
                            const int* __restrict__ off, int* __restrict__ cur,
                            int* __restrict__ csr, int nE)
{
    int i = blockIdx.x * blockDim.x + threadIdx.x;
    int is64 = g_is64;
    if (i < nE) {
        int s = load_idx(ei, i, is64);
        int d = load_idx(ei, (long)nE + i, is64);
        if ((unsigned)s < NODES && (unsigned)d < NODES) {
            int pos = off[d] + atomicAdd(&cur[d], 1);
            csr[pos] = s;
        }
    }
}

// ---------------- tf32 helpers -----------------------------------------------
__device__ __forceinline__ unsigned f2tf(float f) {
    unsigned u;
    asm("cvt.rna.tf32.f32 %0, %1;" : "=r"(u) : "f"(f));
    return u;
}

// ---------------- fused SAGE layer (tf32 mma.sync) ---------------------------
// A = [agg | root] (64 x 256 tf32), B = [Wl ; Wr]^T (128 x 256 tf32, chunked).
// out = relu(A @ Bstacked + b)   [+ optional fused FC head 128->2]
//
// smem layout (words):
//   sA    [64][260]   activations, tf32 bits (cols 0-127 agg, 128-255 root)
//   sW    [128][68]   weight chunk, transposed, tf32 bits
//   sBias [128]       bias (float)
//   sFc   [256]       Wfc  (float, FUSE_FC only)
#define SA_STRIDE 260
#define SW_STRIDE 68
#define SMEM_WORDS (64 * SA_STRIDE + 128 * SW_STRIDE + 128 + 256)

template <int FUSE_FC>
__global__ __launch_bounds__(256) void sage_layer_kernel(
    const int* __restrict__ off, const int* __restrict__ csr,
    const float* __restrict__ feat,
    const float* __restrict__ Wl, const float* __restrict__ Wr,
    const float* __restrict__ bias,
    const float* __restrict__ Wfc, const float* __restrict__ bfc,
    float* __restrict__ out, int n)
{
    extern __shared__ unsigned smem_u[];
    unsigned* sA = smem_u;
    unsigned* sW = smem_u + 64 * SA_STRIDE;
    float* sBias = (float*)(smem_u + 64 * SA_STRIDE + 128 * SW_STRIDE);
    float* sFc   = sBias + 128;

    int tid  = threadIdx.x;
    int w    = tid >> 5;
    int lane = tid & 31;
    int g    = lane >> 2;       // mma group id (0..7)
    int t    = lane & 3;        // mma thread-in-group (0..3)
    int rowBase = blockIdx.x * 64;

    // ---------- Phase A: gather neighbor means (warp w -> rows w*8..w*8+7) ---
    for (int r = 0; r < 8; r++) {
        int rl = w * 8 + r;
        int row = rowBase + rl;
        float4 a0 = make_float4(0.f, 0.f, 0.f, 0.f);
        float4 a1 = make_float4(0.f, 0.f, 0.f, 0.f);
        float4 a2 = make_float4(0.f, 0.f, 0.f, 0.f);
        float4 a3 = make_float4(0.f, 0.f, 0.f, 0.f);
        float inv = 0.f;
        if (row < n) {
            int o0 = __ldg(&off[row]), o1 = __ldg(&off[row + 1]);
            int e = o0;
            for (; e + 3 < o1; e += 4) {
                int i0 = __ldg(&csr[e]);
                int i1 = __ldg(&csr[e + 1]);
                int i2 = __ldg(&csr[e + 2]);
                int i3 = __ldg(&csr[e + 3]);
                float4 v0 = ((const float4*)(feat + (long)i0 * F))[lane];
                float4 v1 = ((const float4*)(feat + (long)i1 * F))[lane];
                float4 v2 = ((const float4*)(feat + (long)i2 * F))[lane];
                float4 v3 = ((const float4*)(feat + (long)i3 * F))[lane];
                a0.x += v0.x; a0.y += v0.y; a0.z += v0.z; a0.w += v0.w;
                a1.x += v1.x; a1.y += v1.y; a1.z += v1.z; a1.w += v1.w;
                a2.x += v2.x; a2.y += v2.y; a2.z += v2.z; a2.w += v2.w;
                a3.x += v3.x; a3.y += v3.y; a3.z += v3.z; a3.w += v3.w;
            }
            for (; e < o1; e++) {
                int i0 = __ldg(&csr[e]);
                float4 v0 = ((const float4*)(feat + (long)i0 * F))[lane];
                a0.x += v0.x; a0.y += v0.y; a0.z += v0.z; a0.w += v0.w;
            }
            inv = 1.0f / fmaxf((float)(o1 - o0), 1.0f);
        }
        uint4 st;
        st.x = f2tf((a0.x + a1.x + a2.x + a3.x) * inv);
        st.y = f2tf((a0.y + a1.y + a2.y + a3.y) * inv);
        st.z = f2tf((a0.z + a1.z + a2.z + a3.z) * inv);
        st.w = f2tf((a0.w + a1.w + a2.w + a3.w) * inv);
        ((uint4*)(sA + rl * SA_STRIDE))[lane] = st;   // cols 0..127
    }
    // root rows -> cols 128..255
#pragma unroll
    for (int i = 0; i < 8; i++) {
        int idx = tid + 256 * i;          // 0..2047 over 64 rows x 32 float4
        int rl = idx >> 5;
        int c4 = idx & 31;
        int row = rowBase + rl;
        float4 v = make_float4(0.f, 0.f, 0.f, 0.f);
        if (row < n) v = ((const float4*)(feat + (long)row * F))[c4];
        uint4 st;
        st.x = f2tf(v.x); st.y = f2tf(v.y); st.z = f2tf(v.z); st.w = f2tf(v.w);
        *(uint4*)(sA + rl * SA_STRIDE + 128 + c4 * 4) = st;
    }
    if (tid < 128) sBias[tid] = bias[tid];
    if (FUSE_FC) sFc[tid] = Wfc[tid];

    // ---------- Phase B: tf32 mma.sync over K=256 in 4 chunks of 64 ----------
    // warp tile: 16 rows x 64 cols; warp grid 4x2
    int rowBlk = (w >> 1) * 16;
    int colBlk = (w & 1) * 64;
    float acc[8][4];
#pragma unroll
    for (int j = 0; j < 8; j++)
#pragma unroll
        for (int d = 0; d < 4; d++) acc[j][d] = 0.f;

    for (int kt = 0; kt < 4; kt++) {
        __syncthreads();
        // load + transpose 64k x 128c weight chunk into sW[c][k]
        const float* Wsrc = (kt < 2) ? Wl : Wr;
        int kbase = (kt & 1) * 64;
#pragma unroll 8
        for (int i = 0; i < 32; i++) {
            int idx = tid + 256 * i;      // 0..8191
            int k = idx >> 7;             // 0..63
            int c = idx & 127;
            sW[c * SW_STRIDE + k] = f2tf(Wsrc[(kbase + k) * 128 + c]);
        }
        __syncthreads();
#pragma unroll
        for (int ks = 0; ks < 8; ks++) {
            int kkA = kt * 64 + ks * 8;   // global k for A
            int kkW = ks * 8;             // local k within sW chunk
            unsigned a0 = sA[(rowBlk + g) * SA_STRIDE + kkA + t];
            unsigned a1 = sA[(rowBlk + g + 8) * SA_STRIDE + kkA + t];
            unsigned a2 = sA[(rowBlk + g) * SA_STRIDE + kkA + t + 4];
            unsigned a3 = sA[(rowBlk + g + 8) * SA_STRIDE + kkA + t + 4];
#pragma unroll
            for (int j = 0; j < 8; j++) {
                unsigned b0 = sW[(colBlk + j * 8 + g) * SW_STRIDE + kkW + t];
                unsigned b1 = sW[(colBlk + j * 8 + g) * SW_STRIDE + kkW + t + 4];
                asm volatile(
                    "mma.sync.aligned.m16n8k8.row.col.f32.tf32.tf32.f32 "
                    "{%0,%1,%2,%3}, {%4,%5,%6,%7}, {%8,%9}, {%0,%1,%2,%3};"
                    : "+f"(acc[j][0]), "+f"(acc[j][1]),
                      "+f"(acc[j][2]), "+f"(acc[j][3])
                    : "r"(a0), "r"(a1), "r"(a2), "r"(a3), "r"(b0), "r"(b1));
            }
        }
    }

    // ---------- epilogue -----------------------------------------------------
    if (!FUSE_FC) {
#pragma unroll
        for (int j = 0; j < 8; j++) {
            int col = colBlk + j * 8 + 2 * t;
            float bc0 = sBias[col], bc1 = sBias[col + 1];
            int row0 = rowBase + rowBlk + g;
            int row1 = row0 + 8;
            if (row0 < n) {
                float2 o;
                o.x = fmaxf(acc[j][0] + bc0, 0.f);
                o.y = fmaxf(acc[j][1] + bc1, 0.f);
                *(float2*)(out + (long)row0 * F + col) = o;
            }
            if (row1 < n) {
                float2 o;
                o.x = fmaxf(acc[j][2] + bc0, 0.f);
                o.y = fmaxf(acc[j][3] + bc1, 0.f);
                *(float2*)(out + (long)row1 * F + col) = o;
            }
        }
    } else {
        // store relu'd h into sA (float bits), then 128->2 FC reduction
        float* sH = (float*)sA;
        __syncthreads();   // all warps done reading sA cols for mma
#pragma unroll
        for (int j = 0; j < 8; j++) {
            int col = colBlk + j * 8 + 2 * t;
            float bc0 = sBias[col], bc1 = sBias[col + 1];
            int r0 = rowBlk + g;
            float2 h0, h1;
            h0.x = fmaxf(acc[j][0] + bc0, 0.f);
            h0.y = fmaxf(acc[j][1] + bc1, 0.f);
            h1.x = fmaxf(acc[j][2] + bc0, 0.f);
            h1.y = fmaxf(acc[j][3] + bc1, 0.f);
            *(float2*)(sH + r0 * SA_STRIDE + col) = h0;
            *(float2*)(sH + (r0 + 8) * SA_STRIDE + col) = h1;
        }
        __syncthreads();
        // warp w handles rows w*8..w*8+7; lane covers 4 cols
        for (int r = 0; r < 8; r++) {
            int rl = w * 8 + r;
            int row = rowBase + rl;
            const float* hr = sH + rl * SA_STRIDE + lane * 4;
            float h0 = hr[0], h1 = hr[1], h2 = hr[2], h3 = hr[3];
            int c0 = lane * 4;
            float p0 = h0 * sFc[(c0 + 0) * 2 + 0] + h1 * sFc[(c0 + 1) * 2 + 0]
                     + h2 * sFc[(c0 + 2) * 2 + 0] + h3 * sFc[(c0 + 3) * 2 + 0];
            float p1 = h0 * sFc[(c0 + 0) * 2 + 1] + h1 * sFc[(c0 + 1) * 2 + 1]
                     + h2 * sFc[(c0 + 2) * 2 + 1] + h3 * sFc[(c0 + 3) * 2 + 1];
#pragma unroll
            for (int d = 16; d > 0; d >>= 1) {
                p0 += __shfl_xor_sync(0xFFFFFFFFu, p0, d);
                p1 += __shfl_xor_sync(0xFFFFFFFFu, p1, d);
            }
            if (lane == 0 && row < n) {
                float2 o;
                o.x = p0 + __ldg(&bfc[0]);
                o.y = p1 + __ldg(&bfc[1]);
                ((float2*)out)[row] = o;
            }
        }
    }
}

// -----------------------------------------------------------------------------
extern "C" void kernel_launch(void* const* d_in, const int* in_sizes, int n_in,
                              void* d_out, int out_size)
{
    const float* x    = (const float*)d_in[0];
    const void*  ei   = d_in[1];                 // int32 or int64, auto-detected
    const float* W1l  = (const float*)d_in[2];
    const float* W1r  = (const float*)d_in[3];
    const float* b1   = (const float*)d_in[4];
    const float* W2l  = (const float*)d_in[5];
    const float* W2r  = (const float*)d_in[6];
    const float* b2   = (const float*)d_in[7];
    const float* Wfc  = (const float*)d_in[8];
    const float* bfc  = (const float*)d_in[9];
    float*       out  = (float*)d_out;

    int n  = in_sizes[0] / F;       // 50000
    int nE = in_sizes[1] / 2;       // 800000

    int *cnt, *off, *cur, *csr, *part;
    float *h1;
    cudaGetSymbolAddress((void**)&cnt,  g_cnt);
    cudaGetSymbolAddress((void**)&off,  g_off);
    cudaGetSymbolAddress((void**)&cur,  g_cur);
    cudaGetSymbolAddress((void**)&csr,  g_csr);
    cudaGetSymbolAddress((void**)&part, g_part);
    cudaGetSymbolAddress((void**)&h1,   g_h1);

    const int SMEM = SMEM_WORDS * 4;   // 102,912 bytes
    cudaFuncSetAttribute(sage_layer_kernel<0>,
                         cudaFuncAttributeMaxDynamicSharedMemorySize, SMEM);
    cudaFuncSetAttribute(sage_layer_kernel<1>,
                         cudaFuncAttributeMaxDynamicSharedMemorySize, SMEM);

    detect_kernel<<<1, 256>>>((const int*)ei);

    // ---- CSR build (once, reused for both layers) ----
    int nb = (n + 1023) / 1024;                 // 49
    zero2_kernel<<<32, 256>>>(cnt, cur, (n + 3) / 4);
    count_kernel<<<(nE + 255) / 256, 256>>>(ei, cnt, nE);
    scan1_kernel<<<nb, 1024>>>(cnt, off, part, n);
    scan2_kernel<<<1, 32>>>(part, nb);
    scan3_kernel<<<nb, 1024>>>(off, part, n, nb);
    fill_kernel<<<(nE + 255) / 256, 256>>>(ei, off, cur, csr, nE);

    int blocks = (n + 63) / 64;

    // ---- layer 1 (writes h1) ----
    sage_layer_kernel<0><<<blocks, 256, SMEM>>>(
        off, csr, x, W1l, W1r, b1, (const float*)0, (const float*)0, h1, n);

    // ---- layer 2 + FC head fused (writes logits) ----
    sage_layer_kernel<1><<<blocks, 256, SMEM>>>(
        off, csr, h1, W2l, W2r, b2, Wfc, bfc, out, n);
}

// round 13
// speedup vs baseline: 1.1414x; 1.1414x over previous
#include <cuda_runtime.h>

#define NODES 50000
#define NEDGES 800000
#define F 128

// ---------------- scratch (device globals; no runtime allocation) ------------
__device__ int   g_cnt[NODES];
__device__ int   g_off[NODES + 1];
__device__ int   g_cur[NODES];
__device__ int   g_csr[NEDGES];
__device__ int   g_part[64];
__device__ float g_h1[NODES * F];
__device__ int   g_is64;

// ---------------- index dtype detection --------------------------------------
__global__ void detect_kernel(const int* __restrict__ p) {
    __shared__ int ok;
    if (threadIdx.x == 0) ok = 1;
    __syncthreads();
    if (p[2 * threadIdx.x + 1] != 0) atomicAnd(&ok, 0);
    __syncthreads();
    if (threadIdx.x == 0) g_is64 = ok;
}

__device__ __forceinline__ int load_idx(const void* __restrict__ p, long i, int is64) {
    if (is64) return (int)((const long long*)p)[i];
    return ((const int*)p)[i];
}

// ---------------- zero fill (two arrays in one launch) ------------------------
__global__ void zero2_kernel(int* __restrict__ a, int* __restrict__ b, int n4) {
    int i = blockIdx.x * blockDim.x + threadIdx.x;
    int4 z = make_int4(0, 0, 0, 0);
    for (; i < n4; i += gridDim.x * blockDim.x) {
        ((int4*)a)[i] = z;
        ((int4*)b)[i] = z;
    }
}

// ---------------- CSR build --------------------------------------------------
__global__ void count_kernel(const void* __restrict__ ei, int* __restrict__ cnt, int nE) {
    int i = blockIdx.x * blockDim.x + threadIdx.x;
    int is64 = g_is64;
    if (i < nE) {
        int d = load_idx(ei, (long)nE + i, is64);
        if ((unsigned)d < NODES) atomicAdd(&cnt[d], 1);
    }
}

__global__ __launch_bounds__(1024) void scan1_kernel(
    const int* __restrict__ cnt, int* __restrict__ off, int* __restrict__ part, int n)
{
    __shared__ int wsum[32];
    int tid = threadIdx.x, lane = tid & 31, wid = tid >> 5;
    int g = blockIdx.x * 1024 + tid;
    int v = (g < n) ? cnt[g] : 0;
    int s = v;
#pragma unroll
    for (int d = 1; d < 32; d <<= 1) {
        int t = __shfl_up_sync(0xffffffffu, s, d);
        if (lane >= d) s += t;
    }
    if (lane == 31) wsum[wid] = s;
    __syncthreads();
    if (wid == 0) {
        int ws = wsum[lane];
#pragma unroll
        for (int d = 1; d < 32; d <<= 1) {
            int t = __shfl_up_sync(0xffffffffu, ws, d);
            if (lane >= d) ws += t;
        }
        wsum[lane] = ws;
    }
    __syncthreads();
    int base = wid ? wsum[wid - 1] : 0;
    if (g < n) off[g] = base + s - v;
    if (tid == 1023) part[blockIdx.x] = wsum[31];
}

__global__ void scan2_kernel(int* __restrict__ part, int nb) {
    if (threadIdx.x == 0) {
        int run = 0;
        for (int i = 0; i < nb; i++) { int t = part[i]; part[i] = run; run += t; }
        part[nb] = run;
    }
}

__global__ __launch_bounds__(1024) void scan3_kernel(
    int* __restrict__ off, const int* __restrict__ part, int n, int nb)
{
    int g = blockIdx.x * 1024 + threadIdx.x;
    if (g < n) off[g] += part[blockIdx.x];
    if (g == 0) off[n] = part[nb];
}

__global__ void fill_kernel(const void* __restrict__ ei,
                            const int* __restrict__ off, int* __restrict__ cur,
                            int* __restrict__ csr, int nE)
{
    int i = blockIdx.x * blockDim.x + threadIdx.x;
    int is64 = g_is64;
    if (i < nE) {
        int s = load_idx(ei, i, is64);
        int d = load_idx(ei, (long)nE + i, is64);
        if ((unsigned)s < NODES && (unsigned)d < NODES) {
            int pos = off[d] + atomicAdd(&cur[d], 1);
            csr[pos] = s;
        }
    }
}

// ---------------- fused SAGE layer -------------------------------------------
// out = relu( mean_{j in N(i)} feat[j] @ Wl + feat[i] @ Wr + b )      (FUSE_FC=0)
// out = (the above) @ Wfc + bfc  fused into epilogue                  (FUSE_FC=1)
//
// block: 256 thr (8 warps), 64 rows/block. Phase A: fp32 gather with 8-deep
// MLP. Phase B: dual-GEMM with packed f32x2 FMA (FFMA2).
template <int FUSE_FC>
__global__ __launch_bounds__(256) void sage_layer_kernel(
    const int* __restrict__ off, const int* __restrict__ csr,
    const float* __restrict__ feat,
    const float* __restrict__ Wl, const float* __restrict__ Wr,
    const float* __restrict__ bias,
    const float* __restrict__ Wfc, const float* __restrict__ bfc,
    float* __restrict__ out, int n)
{
    extern __shared__ float smem[];
    float* sAgg  = smem;                    // [64][128]
    float* sRoot = smem + 64 * F;           // [64][128]
    float* sWl   = smem + 2 * 64 * F;       // [32][128]
    float* sWr   = sWl + 32 * F;            // [32][128]
    float* sFc   = sWr + 32 * F;            // [256]

    int tid  = threadIdx.x;
    int w    = tid >> 5;
    int lane = tid & 31;
    int rowBase = blockIdx.x * 64;

    // ---------- Phase A: gather (warp w handles rows w*8 .. w*8+7) ----------
    // 8 feature loads in flight per iteration to cover L2 latency.
    for (int r = 0; r < 8; r++) {
        int rl = w * 8 + r;
        int row = rowBase + rl;
        float4 a0 = make_float4(0.f, 0.f, 0.f, 0.f);
        float4 a1 = make_float4(0.f, 0.f, 0.f, 0.f);
        float4 a2 = make_float4(0.f, 0.f, 0.f, 0.f);
        float4 a3 = make_float4(0.f, 0.f, 0.f, 0.f);
        float inv = 0.f;
        if (row < n) {
            int o0 = __ldg(&off[row]), o1 = __ldg(&off[row + 1]);
            int e = o0;
            for (; e + 7 < o1; e += 8) {
                int i0 = __ldg(&csr[e]);
                int i1 = __ldg(&csr[e + 1]);
                int i2 = __ldg(&csr[e + 2]);
                int i3 = __ldg(&csr[e + 3]);
                int i4 = __ldg(&csr[e + 4]);
                int i5 = __ldg(&csr[e + 5]);
                int i6 = __ldg(&csr[e + 6]);
                int i7 = __ldg(&csr[e + 7]);
                float4 v0 = ((const float4*)(feat + (long)i0 * F))[lane];
                float4 v1 = ((const float4*)(feat + (long)i1 * F))[lane];
                float4 v2 = ((const float4*)(feat + (long)i2 * F))[lane];
                float4 v3 = ((const float4*)(feat + (long)i3 * F))[lane];
                float4 v4 = ((const float4*)(feat + (long)i4 * F))[lane];
                float4 v5 = ((const float4*)(feat + (long)i5 * F))[lane];
                float4 v6 = ((const float4*)(feat + (long)i6 * F))[lane];
                float4 v7 = ((const float4*)(feat + (long)i7 * F))[lane];
                a0.x += v0.x; a0.y += v0.y; a0.z += v0.z; a0.w += v0.w;
                a1.x += v1.x; a1.y += v1.y; a1.z += v1.z; a1.w += v1.w;
                a2.x += v2.x; a2.y += v2.y; a2.z += v2.z; a2.w += v2.w;
                a3.x += v3.x; a3.y += v3.y; a3.z += v3.z; a3.w += v3.w;
                a0.x += v4.x; a0.y += v4.y; a0.z += v4.z; a0.w += v4.w;
                a1.x += v5.x; a1.y += v5.y; a1.z += v5.z; a1.w += v5.w;
                a2.x += v6.x; a2.y += v6.y; a2.z += v6.z; a2.w += v6.w;
                a3.x += v7.x; a3.y += v7.y; a3.z += v7.z; a3.w += v7.w;
            }
            for (; e + 3 < o1; e += 4) {
                int i0 = __ldg(&csr[e]);
                int i1 = __ldg(&csr[e + 1]);
                int i2 = __ldg(&csr[e + 2]);
                int i3 = __ldg(&csr[e + 3]);
                float4 v0 = ((const float4*)(feat + (long)i0 * F))[lane];
                float4 v1 = ((const float4*)(feat + (long)i1 * F))[lane];
                float4 v2 = ((const float4*)(feat + (long)i2 * F))[lane];
                float4 v3 = ((const float4*)(feat + (long)i3 * F))[lane];
                a0.x += v0.x; a0.y += v0.y; a0.z += v0.z; a0.w += v0.w;
                a1.x += v1.x; a1.y += v1.y; a1.z += v1.z; a1.w += v1.w;
                a2.x += v2.x; a2.y += v2.y; a2.z += v2.z; a2.w += v2.w;
                a3.x += v3.x; a3.y += v3.y; a3.z += v3.z; a3.w += v3.w;
            }
            for (; e < o1; e++) {
                int i0 = __ldg(&csr[e]);
                float4 v0 = ((const float4*)(feat + (long)i0 * F))[lane];
                a0.x += v0.x; a0.y += v0.y; a0.z += v0.z; a0.w += v0.w;
            }
            inv = 1.0f / fmaxf((float)(o1 - o0), 1.0f);
        }
        float4 o;
        o.x = (a0.x + a1.x + a2.x + a3.x) * inv;
        o.y = (a0.y + a1.y + a2.y + a3.y) * inv;
        o.z = (a0.z + a1.z + a2.z + a3.z) * inv;
        o.w = (a0.w + a1.w + a2.w + a3.w) * inv;
        ((float4*)&sAgg[rl * F])[lane] = o;
    }
    // root rows: 64 rows x 32 float4 = 2048 float4, 8 per thread
#pragma unroll
    for (int i = 0; i < 8; i++) {
        int idx = tid + 256 * i;
        int row = rowBase + (idx >> 5);
        int c = idx & 31;
        float4 v = make_float4(0.f, 0.f, 0.f, 0.f);
        if (row < n) v = ((const float4*)(feat + (long)row * F))[c];
        ((float4*)sRoot)[idx] = v;
    }
    if (FUSE_FC) sFc[tid] = Wfc[tid];

    // ---------- Phase B: dual-GEMM with FFMA2 --------------------------------
    unsigned long long acc01[8], acc23[8];
#pragma unroll
    for (int r = 0; r < 8; r++) { acc01[r] = 0ull; acc23[r] = 0ull; }

    for (int kt = 0; kt < 4; kt++) {
        __syncthreads();
        const float4* wl4 = (const float4*)(Wl + kt * 32 * F);
        const float4* wr4 = (const float4*)(Wr + kt * 32 * F);
#pragma unroll
        for (int i = 0; i < 4; i++) {
            ((float4*)sWl)[tid + 256 * i] = wl4[tid + 256 * i];
            ((float4*)sWr)[tid + 256 * i] = wr4[tid + 256 * i];
        }
        __syncthreads();
#pragma unroll
        for (int k = 0; k < 32; k++) {
            ulonglong2 wl = ((const ulonglong2*)(sWl + k * F))[lane];
            ulonglong2 wr = ((const ulonglong2*)(sWr + k * F))[lane];
#pragma unroll
            for (int r = 0; r < 8; r++) {
                int rl = w * 8 + r;
                unsigned ai = __float_as_uint(sAgg[rl * F + kt * 32 + k]);
                unsigned xi = __float_as_uint(sRoot[rl * F + kt * 32 + k]);
                unsigned long long a2, x2;
                asm("mov.b64 %0, {%1, %1};" : "=l"(a2) : "r"(ai));
                asm("mov.b64 %0, {%1, %1};" : "=l"(x2) : "r"(xi));
                asm("fma.rn.f32x2 %0, %1, %2, %0;" : "+l"(acc01[r]) : "l"(a2), "l"(wl.x));
                asm("fma.rn.f32x2 %0, %1, %2, %0;" : "+l"(acc23[r]) : "l"(a2), "l"(wl.y));
                asm("fma.rn.f32x2 %0, %1, %2, %0;" : "+l"(acc01[r]) : "l"(x2), "l"(wr.x));
                asm("fma.rn.f32x2 %0, %1, %2, %0;" : "+l"(acc23[r]) : "l"(x2), "l"(wr.y));
            }
        }
    }

    // ---------- epilogue -----------------------------------------------------
    float4 bv = ((const float4*)bias)[lane];
#pragma unroll
    for (int r = 0; r < 8; r++) {
        int row = rowBase + w * 8 + r;
        unsigned u0, u1, u2, u3;
        asm("mov.b64 {%0, %1}, %2;" : "=r"(u0), "=r"(u1) : "l"(acc01[r]));
        asm("mov.b64 {%0, %1}, %2;" : "=r"(u2), "=r"(u3) : "l"(acc23[r]));
        float h0 = fmaxf(__uint_as_float(u0) + bv.x, 0.f);
        float h1 = fmaxf(__uint_as_float(u1) + bv.y, 0.f);
        float h2 = fmaxf(__uint_as_float(u2) + bv.z, 0.f);
        float h3 = fmaxf(__uint_as_float(u3) + bv.w, 0.f);
        if (!FUSE_FC) {
            if (row < n) {
                float4 o; o.x = h0; o.y = h1; o.z = h2; o.w = h3;
                ((float4*)(out + (long)row * F))[lane] = o;
            }
        } else {
            int c0 = lane * 4;
            float p0 = h0 * sFc[(c0 + 0) * 2 + 0] + h1 * sFc[(c0 + 1) * 2 + 0]
                     + h2 * sFc[(c0 + 2) * 2 + 0] + h3 * sFc[(c0 + 3) * 2 + 0];
            float p1 = h0 * sFc[(c0 + 0) * 2 + 1] + h1 * sFc[(c0 + 1) * 2 + 1]
                     + h2 * sFc[(c0 + 2) * 2 + 1] + h3 * sFc[(c0 + 3) * 2 + 1];
#pragma unroll
            for (int d = 16; d > 0; d >>= 1) {
                p0 += __shfl_xor_sync(0xFFFFFFFFu, p0, d);
                p1 += __shfl_xor_sync(0xFFFFFFFFu, p1, d);
            }
            if (lane == 0 && row < n) {
                float2 o;
                o.x = p0 + __ldg(&bfc[0]);
                o.y = p1 + __ldg(&bfc[1]);
                ((float2*)out)[row] = o;
            }
        }
    }
}

// -----------------------------------------------------------------------------
extern "C" void kernel_launch(void* const* d_in, const int* in_sizes, int n_in,
                              void* d_out, int out_size)
{
    const float* x    = (const float*)d_in[0];
    const void*  ei   = d_in[1];                 // int32 or int64, auto-detected
    const float* W1l  = (const float*)d_in[2];
    const float* W1r  = (const float*)d_in[3];
    const float* b1   = (const float*)d_in[4];
    const float* W2l  = (const float*)d_in[5];
    const float* W2r  = (const float*)d_in[6];
    const float* b2   = (const float*)d_in[7];
    const float* Wfc  = (const float*)d_in[8];
    const float* bfc  = (const float*)d_in[9];
    float*       out  = (float*)d_out;

    int n  = in_sizes[0] / F;       // 50000
    int nE = in_sizes[1] / 2;       // 800000

    int *cnt, *off, *cur, *csr, *part;
    float *h1;
    cudaGetSymbolAddress((void**)&cnt,  g_cnt);
    cudaGetSymbolAddress((void**)&off,  g_off);
    cudaGetSymbolAddress((void**)&cur,  g_cur);
    cudaGetSymbolAddress((void**)&csr,  g_csr);
    cudaGetSymbolAddress((void**)&part, g_part);
    cudaGetSymbolAddress((void**)&h1,   g_h1);

    const int SMEM = (64 * F * 2 + 32 * F * 2 + 256) * 4;   // 99,328 bytes
    cudaFuncSetAttribute(sage_layer_kernel<0>,
                         cudaFuncAttributeMaxDynamicSharedMemorySize, SMEM);
    cudaFuncSetAttribute(sage_layer_kernel<1>,
                         cudaFuncAttributeMaxDynamicSharedMemorySize, SMEM);

    detect_kernel<<<1, 256>>>((const int*)ei);

    // ---- CSR build (once, reused for both layers) ----
    int nb = (n + 1023) / 1024;                 // 49
    zero2_kernel<<<32, 256>>>(cnt, cur, (n + 3) / 4);
    count_kernel<<<(nE + 255) / 256, 256>>>(ei, cnt, nE);
    scan1_kernel<<<nb, 1024>>>(cnt, off, part, n);
    scan2_kernel<<<1, 32>>>(part, nb);
    scan3_kernel<<<nb, 1024>>>(off, part, n, nb);
    fill_kernel<<<(nE + 255) / 256, 256>>>(ei, off, cur, csr, nE);

    int blocks = (n + 63) / 64;

    // ---- layer 1 (writes h1) ----
    sage_layer_kernel<0><<<blocks, 256, SMEM>>>(
        off, csr, x, W1l, W1r, b1, (const float*)0, (const float*)0, h1, n);

    // ---- layer 2 + FC head fused (writes logits) ----
    sage_layer_kernel<1><<<blocks, 256, SMEM>>>(
        off, csr, h1, W2l, W2r, b2, Wfc, bfc, out, n);
}

// round 14
// speedup vs baseline: 1.5294x; 1.3399x over previous
#include <cuda_runtime.h>

#define NODES 50000
#define NEDGES 800000
#define F 128

// ---------------- scratch (device globals; no runtime allocation) ------------
__device__ int      g_cnt[NODES];
__device__ int      g_off[NODES + 1];
__device__ int      g_cur[NODES];
__device__ int      g_csr[NEDGES];
__device__ int      g_part[64];
__device__ float    g_h1[NODES * F];
__device__ unsigned g_Wt1[F * 256];     // [c][kk] tf32 bits, kk<128: W1l, else W1r
__device__ unsigned g_Wt2[F * 256];
__device__ int      g_is64;

// ---------------- index dtype detection --------------------------------------
__global__ void detect_kernel(const int* __restrict__ p) {
    __shared__ int ok;
    if (threadIdx.x == 0) ok = 1;
    __syncthreads();
    if (p[2 * threadIdx.x + 1] != 0) atomicAnd(&ok, 0);
    __syncthreads();
    if (threadIdx.x == 0) g_is64 = ok;
}

__device__ __forceinline__ int load_idx(const void* __restrict__ p, long i, int is64) {
    if (is64) return (int)((const long long*)p)[i];
    return ((const int*)p)[i];
}

// ---------------- zero fill (two arrays in one launch) ------------------------
__global__ void zero2_kernel(int* __restrict__ a, int* __restrict__ b, int n4) {
    int i = blockIdx.x * blockDim.x + threadIdx.x;
    int4 z = make_int4(0, 0, 0, 0);
    for (; i < n4; i += gridDim.x * blockDim.x) {
        ((int4*)a)[i] = z;
        ((int4*)b)[i] = z;
    }
}

// ---------------- tf32 helpers -----------------------------------------------
__device__ __forceinline__ unsigned f2tf(float f) {
    unsigned u;
    asm("cvt.rna.tf32.f32 %0, %1;" : "=r"(u) : "f"(f));
    return u;
}

// ---------------- weight prep: Wt[c][kk] = tf32(stack(Wl,Wr)[kk][c]) ---------
__global__ __launch_bounds__(256) void wprep_kernel(
    const float* __restrict__ Wl, const float* __restrict__ Wr,
    unsigned* __restrict__ Wt)
{
    int idx = blockIdx.x * blockDim.x + threadIdx.x;   // 0..32767
    int c  = idx & 127;
    int kk = idx >> 7;
    float v = (kk < 128) ? Wl[kk * F + c] : Wr[(kk - 128) * F + c];
    Wt[c * 256 + kk] = f2tf(v);
}

// ---------------- CSR build --------------------------------------------------
__global__ void count_kernel(const void* __restrict__ ei, int* __restrict__ cnt, int nE) {
    int i = blockIdx.x * blockDim.x + threadIdx.x;
    int is64 = g_is64;
    if (i < nE) {
        int d = load_idx(ei, (long)nE + i, is64);
        if ((unsigned)d < NODES) atomicAdd(&cnt[d], 1);
    }
}

__global__ __launch_bounds__(1024) void scan1_kernel(
    const int* __restrict__ cnt, int* __restrict__ off, int* __restrict__ part, int n)
{
    __shared__ int wsum[32];
    int tid = threadIdx.x, lane = tid & 31, wid = tid >> 5;
    int g = blockIdx.x * 1024 + tid;
    int v = (g < n) ? cnt[g] : 0;
    int s = v;
#pragma unroll
    for (int d = 1; d < 32; d <<= 1) {
        int t = __shfl_up_sync(0xffffffffu, s, d);
        if (lane >= d) s += t;
    }
    if (lane == 31) wsum[wid] = s;
    __syncthreads();
    if (wid == 0) {
        int ws = wsum[lane];
#pragma unroll
        for (int d = 1; d < 32; d <<= 1) {
            int t = __shfl_up_sync(0xffffffffu, ws, d);
            if (lane >= d) ws += t;
        }
        wsum[lane] = ws;
    }
    __syncthreads();
    int base = wid ? wsum[wid - 1] : 0;
    if (g < n) off[g] = base + s - v;
    if (tid == 1023) part[blockIdx.x] = wsum[31];
}

__global__ void scan2_kernel(int* __restrict__ part, int nb) {
    if (threadIdx.x == 0) {
        int run = 0;
        for (int i = 0; i < nb; i++) { int t = part[i]; part[i] = run; run += t; }
        part[nb] = run;
    }
}

__global__ __launch_bounds__(1024) void scan3_kernel(
    int* __restrict__ off, const int* __restrict__ part, int n, int nb)
{
    int g = blockIdx.x * 1024 + threadIdx.x;
    if (g < n) off[g] += part[blockIdx.x];
    if (g == 0) off[n] = part[nb];
}

__global__ void fill_kernel(const void* __restrict__ ei,
                            const int* __restrict__ off, int* __restrict__ cur,
                            int* __restrict__ csr, int nE)
{
    int i = blockIdx.x * blockDim.x + threadIdx.x;
    int is64 = g_is64;
    if (i < nE) {
        int s = load_idx(ei, i, is64);
        int d = load_idx(ei, (long)nE + i, is64);
        if ((unsigned)s < NODES && (unsigned)d < NODES) {
            int pos = off[d] + atomicAdd(&cur[d], 1);
            csr[pos] = s;
        }
    }
}

// ---------------- fused SAGE layer (tf32 mma, pre-transposed weights) --------
// A = [agg | root] (64 x 256 tf32), Wt = [128 c][256 kk] tf32.
// out = relu(A @ Wt^T + b)   [+ optional fused FC head 128->2]
#define SA_STRIDE 260
#define SW_STRIDE 68
#define SMEM_WORDS (64 * SA_STRIDE + 128 * SW_STRIDE + 128 + 256)

template <int FUSE_FC>
__global__ __launch_bounds__(256) void sage_layer_kernel(
    const int* __restrict__ off, const int* __restrict__ csr,
    const float* __restrict__ feat,
    const unsigned* __restrict__ Wt,
    const float* __restrict__ bias,
    const float* __restrict__ Wfc, const float* __restrict__ bfc,
    float* __restrict__ out, int n)
{
    extern __shared__ unsigned smem_u[];
    unsigned* sA = smem_u;                                   // [64][260]
    unsigned* sW = smem_u + 64 * SA_STRIDE;                  // [128][68]
    float* sBias = (float*)(smem_u + 64 * SA_STRIDE + 128 * SW_STRIDE);
    float* sFc   = sBias + 128;

    int tid  = threadIdx.x;
    int w    = tid >> 5;
    int lane = tid & 31;
    int g    = lane >> 2;
    int t    = lane & 3;
    int rowBase = blockIdx.x * 64;

    // ---------- Phase A: gather, MLP-8, tf32 write to sA cols 0..127 ---------
    for (int r = 0; r < 8; r++) {
        int rl = w * 8 + r;
        int row = rowBase + rl;
        float4 a0 = make_float4(0.f, 0.f, 0.f, 0.f);
        float4 a1 = make_float4(0.f, 0.f, 0.f, 0.f);
        float4 a2 = make_float4(0.f, 0.f, 0.f, 0.f);
        float4 a3 = make_float4(0.f, 0.f, 0.f, 0.f);
        float inv = 0.f;
        if (row < n) {
            int o0 = __ldg(&off[row]), o1 = __ldg(&off[row + 1]);
            int e = o0;
            for (; e + 7 < o1; e += 8) {
                int i0 = __ldg(&csr[e]);
                int i1 = __ldg(&csr[e + 1]);
                int i2 = __ldg(&csr[e + 2]);
                int i3 = __ldg(&csr[e + 3]);
                int i4 = __ldg(&csr[e + 4]);
                int i5 = __ldg(&csr[e + 5]);
                int i6 = __ldg(&csr[e + 6]);
                int i7 = __ldg(&csr[e + 7]);
                float4 v0 = ((const float4*)(feat + (long)i0 * F))[lane];
                float4 v1 = ((const float4*)(feat + (long)i1 * F))[lane];
                float4 v2 = ((const float4*)(feat + (long)i2 * F))[lane];
                float4 v3 = ((const float4*)(feat + (long)i3 * F))[lane];
                float4 v4 = ((const float4*)(feat + (long)i4 * F))[lane];
                float4 v5 = ((const float4*)(feat + (long)i5 * F))[lane];
                float4 v6 = ((const float4*)(feat + (long)i6 * F))[lane];
                float4 v7 = ((const float4*)(feat + (long)i7 * F))[lane];
                a0.x += v0.x; a0.y += v0.y; a0.z += v0.z; a0.w += v0.w;
                a1.x += v1.x; a1.y += v1.y; a1.z += v1.z; a1.w += v1.w;
                a2.x += v2.x; a2.y += v2.y; a2.z += v2.z; a2.w += v2.w;
                a3.x += v3.x; a3.y += v3.y; a3.z += v3.z; a3.w += v3.w;
                a0.x += v4.x; a0.y += v4.y; a0.z += v4.z; a0.w += v4.w;
                a1.x += v5.x; a1.y += v5.y; a1.z += v5.z; a1.w += v5.w;
                a2.x += v6.x; a2.y += v6.y; a2.z += v6.z; a2.w += v6.w;
                a3.x += v7.x; a3.y += v7.y; a3.z += v7.z; a3.w += v7.w;
            }
            for (; e + 3 < o1; e += 4) {
                int i0 = __ldg(&csr[e]);
                int i1 = __ldg(&csr[e + 1]);
                int i2 = __ldg(&csr[e + 2]);
                int i3 = __ldg(&csr[e + 3]);
                float4 v0 = ((const float4*)(feat + (long)i0 * F))[lane];
                float4 v1 = ((const float4*)(feat + (long)i1 * F))[lane];
                float4 v2 = ((const float4*)(feat + (long)i2 * F))[lane];
                float4 v3 = ((const float4*)(feat + (long)i3 * F))[lane];
                a0.x += v0.x; a0.y += v0.y; a0.z += v0.z; a0.w += v0.w;
                a1.x += v1.x; a1.y += v1.y; a1.z += v1.z; a1.w += v1.w;
                a2.x += v2.x; a2.y += v2.y; a2.z += v2.z; a2.w += v2.w;
                a3.x += v3.x; a3.y += v3.y; a3.z += v3.z; a3.w += v3.w;
            }
            for (; e < o1; e++) {
                int i0 = __ldg(&csr[e]);
                float4 v0 = ((const float4*)(feat + (long)i0 * F))[lane];
                a0.x += v0.x; a0.y += v0.y; a0.z += v0.z; a0.w += v0.w;
            }
            inv = 1.0f / fmaxf((float)(o1 - o0), 1.0f);
        }
        uint4 st;
        st.x = f2tf((a0.x + a1.x + a2.x + a3.x) * inv);
        st.y = f2tf((a0.y + a1.y + a2.y + a3.y) * inv);
        st.z = f2tf((a0.z + a1.z + a2.z + a3.z) * inv);
        st.w = f2tf((a0.w + a1.w + a2.w + a3.w) * inv);
        ((uint4*)(sA + rl * SA_STRIDE))[lane] = st;
    }
    // root rows -> sA cols 128..255
#pragma unroll
    for (int i = 0; i < 8; i++) {
        int idx = tid + 256 * i;
        int rl = idx >> 5;
        int c4 = idx & 31;
        int row = rowBase + rl;
        float4 v = make_float4(0.f, 0.f, 0.f, 0.f);
        if (row < n) v = ((const float4*)(feat + (long)row * F))[c4];
        uint4 st;
        st.x = f2tf(v.x); st.y = f2tf(v.y); st.z = f2tf(v.z); st.w = f2tf(v.w);
        *(uint4*)(sA + rl * SA_STRIDE + 128 + c4 * 4) = st;
    }
    if (tid < 128) sBias[tid] = bias[tid];
    if (FUSE_FC) sFc[tid] = Wfc[tid];

    // ---------- Phase B: tf32 mma over K=256 in 4 chunks of 64 ---------------
    int rowBlk = (w >> 1) * 16;
    int colBlk = (w & 1) * 64;
    float acc[8][4];
#pragma unroll
    for (int j = 0; j < 8; j++)
#pragma unroll
        for (int d = 0; d < 4; d++) acc[j][d] = 0.f;

    for (int kt = 0; kt < 4; kt++) {
        __syncthreads();
        // stage weight chunk: sW[c][kl] = Wt[c][kt*64 + kl], float4 copies
#pragma unroll
        for (int i = 0; i < 8; i++) {
            int idx = tid + 256 * i;      // 0..2047
            int c   = idx >> 4;           // 0..127
            int kl4 = idx & 15;           // 0..15
            *(uint4*)(sW + c * SW_STRIDE + kl4 * 4) =
                *(const uint4*)(Wt + c * 256 + kt * 64 + kl4 * 4);
        }
        __syncthreads();
#pragma unroll
        for (int ks = 0; ks < 8; ks++) {
            int kkA = kt * 64 + ks * 8;
            int kkW = ks * 8;
            unsigned a0 = sA[(rowBlk + g) * SA_STRIDE + kkA + t];
            unsigned a1 = sA[(rowBlk + g + 8) * SA_STRIDE + kkA + t];
            unsigned a2 = sA[(rowBlk + g) * SA_STRIDE + kkA + t + 4];
            unsigned a3 = sA[(rowBlk + g + 8) * SA_STRIDE + kkA + t + 4];
#pragma unroll
            for (int j = 0; j < 8; j++) {
                unsigned b0 = sW[(colBlk + j * 8 + g) * SW_STRIDE + kkW + t];
                unsigned b1 = sW[(colBlk + j * 8 + g) * SW_STRIDE + kkW + t + 4];
                asm volatile(
                    "mma.sync.aligned.m16n8k8.row.col.f32.tf32.tf32.f32 "
                    "{%0,%1,%2,%3}, {%4,%5,%6,%7}, {%8,%9}, {%0,%1,%2,%3};"
                    : "+f"(acc[j][0]), "+f"(acc[j][1]),
                      "+f"(acc[j][2]), "+f"(acc[j][3])
                    : "r"(a0), "r"(a1), "r"(a2), "r"(a3), "r"(b0), "r"(b1));
            }
        }
    }

    // ---------- epilogue -----------------------------------------------------
    if (!FUSE_FC) {
#pragma unroll
        for (int j = 0; j < 8; j++) {
            int col = colBlk + j * 8 + 2 * t;
            float bc0 = sBias[col], bc1 = sBias[col + 1];
            int row0 = rowBase + rowBlk + g;
            int row1 = row0 + 8;
            if (row0 < n) {
                float2 o;
                o.x = fmaxf(acc[j][0] + bc0, 0.f);
                o.y = fmaxf(acc[j][1] + bc1, 0.f);
                *(float2*)(out + (long)row0 * F + col) = o;
            }
            if (row1 < n) {
                float2 o;
                o.x = fmaxf(acc[j][2] + bc0, 0.f);
                o.y = fmaxf(acc[j][3] + bc1, 0.f);
                *(float2*)(out + (long)row1 * F + col) = o;
            }
        }
    } else {
        float* sH = (float*)sA;
        __syncthreads();
#pragma unroll
        for (int j = 0; j < 8; j++) {
            int col = colBlk + j * 8 + 2 * t;
            float bc0 = sBias[col], bc1 = sBias[col + 1];
            int r0 = rowBlk + g;
            float2 h0, h1;
            h0.x = fmaxf(acc[j][0] + bc0, 0.f);
            h0.y = fmaxf(acc[j][1] + bc1, 0.f);
            h1.x = fmaxf(acc[j][2] + bc0, 0.f);
            h1.y = fmaxf(acc[j][3] + bc1, 0.f);
            *(float2*)(sH + r0 * SA_STRIDE + col) = h0;
            *(float2*)(sH + (r0 + 8) * SA_STRIDE + col) = h1;
        }
        __syncthreads();
        for (int r = 0; r < 8; r++) {
            int rl = w * 8 + r;
            int row = rowBase + rl;
            const float* hr = sH + rl * SA_STRIDE + lane * 4;
            float h0 = hr[0], h1 = hr[1], h2 = hr[2], h3 = hr[3];
            int c0 = lane * 4;
            float p0 = h0 * sFc[(c0 + 0) * 2 + 0] + h1 * sFc[(c0 + 1) * 2 + 0]
                     + h2 * sFc[(c0 + 2) * 2 + 0] + h3 * sFc[(c0 + 3) * 2 + 0];
            float p1 = h0 * sFc[(c0 + 0) * 2 + 1] + h1 * sFc[(c0 + 1) * 2 + 1]
                     + h2 * sFc[(c0 + 2) * 2 + 1] + h3 * sFc[(c0 + 3) * 2 + 1];
#pragma unroll
            for (int d = 16; d > 0; d >>= 1) {
                p0 += __shfl_xor_sync(0xFFFFFFFFu, p0, d);
                p1 += __shfl_xor_sync(0xFFFFFFFFu, p1, d);
            }
            if (lane == 0 && row < n) {
                float2 o;
                o.x = p0 + __ldg(&bfc[0]);
                o.y = p1 + __ldg(&bfc[1]);
                ((float2*)out)[row] = o;
            }
        }
    }
}

// -----------------------------------------------------------------------------
extern "C" void kernel_launch(void* const* d_in, const int* in_sizes, int n_in,
                              void* d_out, int out_size)
{
    const float* x    = (const float*)d_in[0];
    const void*  ei   = d_in[1];                 // int32 or int64, auto-detected
    const float* W1l  = (const float*)d_in[2];
    const float* W1r  = (const float*)d_in[3];
    const float* b1   = (const float*)d_in[4];
    const float* W2l  = (const float*)d_in[5];
    const float* W2r  = (const float*)d_in[6];
    const float* b2   = (const float*)d_in[7];
    const float* Wfc  = (const float*)d_in[8];
    const float* bfc  = (const float*)d_in[9];
    float*       out  = (float*)d_out;

    int n  = in_sizes[0] / F;       // 50000
    int nE = in_sizes[1] / 2;       // 800000

    int *cnt, *off, *cur, *csr, *part;
    float *h1;
    unsigned *Wt1, *Wt2;
    cudaGetSymbolAddress((void**)&cnt,  g_cnt);
    cudaGetSymbolAddress((void**)&off,  g_off);
    cudaGetSymbolAddress((void**)&cur,  g_cur);
    cudaGetSymbolAddress((void**)&csr,  g_csr);
    cudaGetSymbolAddress((void**)&part, g_part);
    cudaGetSymbolAddress((void**)&h1,   g_h1);
    cudaGetSymbolAddress((void**)&Wt1,  g_Wt1);
    cudaGetSymbolAddress((void**)&Wt2,  g_Wt2);

    const int SMEM = SMEM_WORDS * 4;   // 102,912 bytes
    cudaFuncSetAttribute(sage_layer_kernel<0>,
                         cudaFuncAttributeMaxDynamicSharedMemorySize, SMEM);
    cudaFuncSetAttribute(sage_layer_kernel<1>,
                         cudaFuncAttributeMaxDynamicSharedMemorySize, SMEM);

    detect_kernel<<<1, 256>>>((const int*)ei);

    // ---- weight prep (once) ----
    wprep_kernel<<<128, 256>>>(W1l, W1r, Wt1);
    wprep_kernel<<<128, 256>>>(W2l, W2r, Wt2);

    // ---- CSR build (once, reused for both layers) ----
    int nb = (n + 1023) / 1024;                 // 49
    zero2_kernel<<<32, 256>>>(cnt, cur, (n + 3) / 4);
    count_kernel<<<(nE + 255) / 256, 256>>>(ei, cnt, nE);
    scan1_kernel<<<nb, 1024>>>(cnt, off, part, n);
    scan2_kernel<<<1, 32>>>(part, nb);
    scan3_kernel<<<nb, 1024>>>(off, part, n, nb);
    fill_kernel<<<(nE + 255) / 256, 256>>>(ei, off, cur, csr, nE);

    int blocks = (n + 63) / 64;

    // ---- layer 1 (writes h1) ----
    sage_layer_kernel<0><<<blocks, 256, SMEM>>>(
        off, csr, x, Wt1, b1, (const float*)0, (const float*)0, h1, n);

    // ---- layer 2 + FC head fused (writes logits) ----
    sage_layer_kernel<1><<<blocks, 256, SMEM>>>(
        off, csr, h1, Wt2, b2, Wfc, bfc, out, n);
}

// round 17
// speedup vs baseline: 1.5355x; 1.0040x over previous
#include <cuda_runtime.h>

#define NODES 50000
#define NEDGES 800000
#define F 128

// ---------------- scratch (device globals; no runtime allocation) ------------
__device__ int      g_cnt[NODES];
__device__ int      g_off[NODES + 1];
__device__ int      g_cur[NODES];
__device__ int      g_csr[NEDGES];
__device__ int      g_part[64];
__device__ float    g_h1[NODES * F];
__device__ unsigned g_Wt1[F * 256];     // [c][kk] tf32 bits, kk<128: W1l, else W1r
__device__ unsigned g_Wt2[F * 256];
__device__ int      g_is64;

// ---------------- index dtype detection --------------------------------------
__global__ void detect_kernel(const int* __restrict__ p) {
    __shared__ int ok;
    if (threadIdx.x == 0) ok = 1;
    __syncthreads();
    if (p[2 * threadIdx.x + 1] != 0) atomicAnd(&ok, 0);
    __syncthreads();
    if (threadIdx.x == 0) g_is64 = ok;
}

__device__ __forceinline__ int load_idx(const void* __restrict__ p, long i, int is64) {
    if (is64) return (int)((const long long*)p)[i];
    return ((const int*)p)[i];
}

// ---------------- zero fill (two arrays in one launch) ------------------------
__global__ void zero2_kernel(int* __restrict__ a, int* __restrict__ b, int n4) {
    int i = blockIdx.x * blockDim.x + threadIdx.x;
    int4 z = make_int4(0, 0, 0, 0);
    for (; i < n4; i += gridDim.x * blockDim.x) {
        ((int4*)a)[i] = z;
        ((int4*)b)[i] = z;
    }
}

// ---------------- tf32 helpers -----------------------------------------------
__device__ __forceinline__ unsigned f2tf(float f) {
    unsigned u;
    asm("cvt.rna.tf32.f32 %0, %1;" : "=r"(u) : "f"(f));
    return u;
}

// ---------------- weight prep: both layers in one launch ---------------------
__global__ __launch_bounds__(256) void wprep_kernel(
    const float* __restrict__ W1l, const float* __restrict__ W1r,
    const float* __restrict__ W2l, const float* __restrict__ W2r,
    unsigned* __restrict__ Wt1, unsigned* __restrict__ Wt2)
{
    int idx = blockIdx.x * blockDim.x + threadIdx.x;   // 0..65535
    int layer = idx >> 15;
    int j = idx & 32767;
    int c  = j & 127;
    int kk = j >> 7;
    const float* Wl = layer ? W2l : W1l;
    const float* Wr = layer ? W2r : W1r;
    unsigned* Wt = layer ? Wt2 : Wt1;
    float v = (kk < 128) ? Wl[kk * F + c] : Wr[(kk - 128) * F + c];
    Wt[c * 256 + kk] = f2tf(v);
}

// ---------------- CSR build --------------------------------------------------
// 2 edges per thread, vectorized dst loads.
__global__ void count_kernel(const void* __restrict__ ei, int* __restrict__ cnt, int nE) {
    int i = blockIdx.x * blockDim.x + threadIdx.x;     // pair index
    int is64 = g_is64;
    int base = i * 2;
    if (base >= nE) return;
    int d0, d1;
    if (is64) {
        longlong2 v = ((const longlong2*)((const long long*)ei + nE))[i];
        d0 = (int)v.x; d1 = (int)v.y;
    } else {
        int2 v = ((const int2*)((const int*)ei + nE))[i];
        d0 = v.x; d1 = v.y;
    }
    if ((unsigned)d0 < NODES) atomicAdd(&cnt[d0], 1);
    if (base + 1 < nE && (unsigned)d1 < NODES) atomicAdd(&cnt[d1], 1);
}

__global__ __launch_bounds__(1024) void scan1_kernel(
    const int* __restrict__ cnt, int* __restrict__ off, int* __restrict__ part, int n)
{
    __shared__ int wsum[32];
    int tid = threadIdx.x, lane = tid & 31, wid = tid >> 5;
    int g = blockIdx.x * 1024 + tid;
    int v = (g < n) ? cnt[g] : 0;
    int s = v;
#pragma unroll
    for (int d = 1; d < 32; d <<= 1) {
        int t = __shfl_up_sync(0xffffffffu, s, d);
        if (lane >= d) s += t;
    }
    if (lane == 31) wsum[wid] = s;
    __syncthreads();
    if (wid == 0) {
        int ws = wsum[lane];
#pragma unroll
        for (int d = 1; d < 32; d <<= 1) {
            int t = __shfl_up_sync(0xffffffffu, ws, d);
            if (lane >= d) ws += t;
        }
        wsum[lane] = ws;
    }
    __syncthreads();
    int base = wid ? wsum[wid - 1] : 0;
    if (g < n) off[g] = base + s - v;
    if (tid == 1023) part[blockIdx.x] = wsum[31];
}

// scan3 now self-computes the exclusive prefix of part[] (nb <= 64)
__global__ __launch_bounds__(1024) void scan3_kernel(
    int* __restrict__ off, const int* __restrict__ part, int n, int nb)
{
    __shared__ int sprefix;   // exclusive prefix for this block
    __shared__ int stotal;
    int tid = threadIdx.x, lane = tid & 31;
    if (tid < 32) {
        // two-segment inclusive scan over up to 64 entries
        int v0 = (lane < nb) ? part[lane] : 0;
        int v1 = (lane + 32 < nb) ? part[lane + 32] : 0;
        int s0 = v0;
#pragma unroll
        for (int d = 1; d < 32; d <<= 1) {
            int t = __shfl_up_sync(0xffffffffu, s0, d);
            if (lane >= d) s0 += t;
        }
        int tot0 = __shfl_sync(0xffffffffu, s0, 31);
        int s1 = v1;
#pragma unroll
        for (int d = 1; d < 32; d <<= 1) {
            int t = __shfl_up_sync(0xffffffffu, s1, d);
            if (lane >= d) s1 += t;
        }
        s1 += tot0;
        int tot1 = __shfl_sync(0xffffffffu, s1, 31);
        // exclusive prefix for index bid
        int bid = blockIdx.x;
        int incl = (bid < 32) ? __shfl_sync(0xffffffffu, s0, bid & 31)
                              : __shfl_sync(0xffffffffu, s1, bid & 31);
        int val  = (bid < nb) ? ((bid < 32) ? __shfl_sync(0xffffffffu, v0, bid & 31)
                                            : __shfl_sync(0xffffffffu, v1, bid & 31)) : 0;
        if (lane == 0) { sprefix = incl - val; stotal = tot1; }
    }
    __syncthreads();
    int g = blockIdx.x * 1024 + tid;
    if (g < n) off[g] += sprefix;
    if (g == 0) off[n] = stotal;
}

// 2 edges per thread, vectorized src+dst loads.
__global__ void fill_kernel(const void* __restrict__ ei,
                            const int* __restrict__ off, int* __restrict__ cur,
                            int* __restrict__ csr, int nE)
{
    int i = blockIdx.x * blockDim.x + threadIdx.x;     // pair index
    int is64 = g_is64;
    int base = i * 2;
    if (base >= nE) return;
    int s0, s1, d0, d1;
    if (is64) {
        longlong2 sv = ((const longlong2*)ei)[i];
        longlong2 dv = ((const longlong2*)((const long long*)ei + nE))[i];
        s0 = (int)sv.x; s1 = (int)sv.y;
        d0 = (int)dv.x; d1 = (int)dv.y;
    } else {
        int2 sv = ((const int2*)ei)[i];
        int2 dv = ((const int2*)((const int*)ei + nE))[i];
        s0 = sv.x; s1 = sv.y;
        d0 = dv.x; d1 = dv.y;
    }
    if ((unsigned)s0 < NODES && (unsigned)d0 < NODES) {
        int pos = off[d0] + atomicAdd(&cur[d0], 1);
        csr[pos] = s0;
    }
    if (base + 1 < nE && (unsigned)s1 < NODES && (unsigned)d1 < NODES) {
        int pos = off[d1] + atomicAdd(&cur[d1], 1);
        csr[pos] = s1;
    }
}

// ---------------- fused SAGE layer (tf32 mma, pre-transposed weights) --------
// A = [agg | root] (64 x 256 tf32), Wt = [128 c][256 kk] tf32.
// out = relu(A @ Wt^T + b)   [+ optional fused FC head 128->2]
#define SA_STRIDE 260
#define SW_STRIDE 68
#define SMEM_WORDS (64 * SA_STRIDE + 128 * SW_STRIDE + 128 + 256)

template <int FUSE_FC>
__global__ __launch_bounds__(256) void sage_layer_kernel(
    const int* __restrict__ off, const int* __restrict__ csr,
    const float* __restrict__ feat,
    const unsigned* __restrict__ Wt,
    const float* __restrict__ bias,
    const float* __restrict__ Wfc, const float* __restrict__ bfc,
    float* __restrict__ out, int n)
{
    extern __shared__ unsigned smem_u[];
    unsigned* sA = smem_u;                                   // [64][260]
    unsigned* sW = smem_u + 64 * SA_STRIDE;                  // [128][68]
    float* sBias = (float*)(smem_u + 64 * SA_STRIDE + 128 * SW_STRIDE);
    float* sFc   = sBias + 128;

    int tid  = threadIdx.x;
    int w    = tid >> 5;
    int lane = tid & 31;
    int g    = lane >> 2;
    int t    = lane & 3;
    int rowBase = blockIdx.x * 64;

    // ---------- root rows first: independent streaming loads issue early ----
#pragma unroll
    for (int i = 0; i < 8; i++) {
        int idx = tid + 256 * i;
        int rl = idx >> 5;
        int c4 = idx & 31;
        int row = rowBase + rl;
        float4 v = make_float4(0.f, 0.f, 0.f, 0.f);
        if (row < n) v = ((const float4*)(feat + (long)row * F))[c4];
        uint4 st;
        st.x = f2tf(v.x); st.y = f2tf(v.y); st.z = f2tf(v.z); st.w = f2tf(v.w);
        *(uint4*)(sA + rl * SA_STRIDE + 128 + c4 * 4) = st;
    }
    if (tid < 128) sBias[tid] = bias[tid];
    if (FUSE_FC) sFc[tid] = Wfc[tid];

    // ---------- Phase A: gather, MLP-8, tf32 write to sA cols 0..127 ---------
    for (int r = 0; r < 8; r++) {
        int rl = w * 8 + r;
        int row = rowBase + rl;
        float4 a0 = make_float4(0.f, 0.f, 0.f, 0.f);
        float4 a1 = make_float4(0.f, 0.f, 0.f, 0.f);
        float4 a2 = make_float4(0.f, 0.f, 0.f, 0.f);
        float4 a3 = make_float4(0.f, 0.f, 0.f, 0.f);
        float inv = 0.f;
        if (row < n) {
            int o0 = __ldg(&off[row]), o1 = __ldg(&off[row + 1]);
            int e = o0;
            for (; e + 7 < o1; e += 8) {
                int i0 = __ldg(&csr[e]);
                int i1 = __ldg(&csr[e + 1]);
                int i2 = __ldg(&csr[e + 2]);
                int i3 = __ldg(&csr[e + 3]);
                int i4 = __ldg(&csr[e + 4]);
                int i5 = __ldg(&csr[e + 5]);
                int i6 = __ldg(&csr[e + 6]);
                int i7 = __ldg(&csr[e + 7]);
                float4 v0 = ((const float4*)(feat + (long)i0 * F))[lane];
                float4 v1 = ((const float4*)(feat + (long)i1 * F))[lane];
                float4 v2 = ((const float4*)(feat + (long)i2 * F))[lane];
                float4 v3 = ((const float4*)(feat + (long)i3 * F))[lane];
                float4 v4 = ((const float4*)(feat + (long)i4 * F))[lane];
                float4 v5 = ((const float4*)(feat + (long)i5 * F))[lane];
                float4 v6 = ((const float4*)(feat + (long)i6 * F))[lane];
                float4 v7 = ((const float4*)(feat + (long)i7 * F))[lane];
                a0.x += v0.x; a0.y += v0.y; a0.z += v0.z; a0.w += v0.w;
                a1.x += v1.x; a1.y += v1.y; a1.z += v1.z; a1.w += v1.w;
                a2.x += v2.x; a2.y += v2.y; a2.z += v2.z; a2.w += v2.w;
                a3.x += v3.x; a3.y += v3.y; a3.z += v3.z; a3.w += v3.w;
                a0.x += v4.x; a0.y += v4.y; a0.z += v4.z; a0.w += v4.w;
                a1.x += v5.x; a1.y += v5.y; a1.z += v5.z; a1.w += v5.w;
                a2.x += v6.x; a2.y += v6.y; a2.z += v6.z; a2.w += v6.w;
                a3.x += v7.x; a3.y += v7.y; a3.z += v7.z; a3.w += v7.w;
            }
            for (; e + 3 < o1; e += 4) {
                int i0 = __ldg(&csr[e]);
                int i1 = __ldg(&csr[e + 1]);
                int i2 = __ldg(&csr[e + 2]);
                int i3 = __ldg(&csr[e + 3]);
                float4 v0 = ((const float4*)(feat + (long)i0 * F))[lane];
                float4 v1 = ((const float4*)(feat + (long)i1 * F))[lane];
                float4 v2 = ((const float4*)(feat + (long)i2 * F))[lane];
                float4 v3 = ((const float4*)(feat + (long)i3 * F))[lane];
                a0.x += v0.x; a0.y += v0.y; a0.z += v0.z; a0.w += v0.w;
                a1.x += v1.x; a1.y += v1.y; a1.z += v1.z; a1.w += v1.w;
                a2.x += v2.x; a2.y += v2.y; a2.z += v2.z; a2.w += v2.w;
                a3.x += v3.x; a3.y += v3.y; a3.z += v3.z; a3.w += v3.w;
            }
            for (; e < o1; e++) {
                int i0 = __ldg(&csr[e]);
                float4 v0 = ((const float4*)(feat + (long)i0 * F))[lane];
                a0.x += v0.x; a0.y += v0.y; a0.z += v0.z; a0.w += v0.w;
            }
            inv = 1.0f / fmaxf((float)(o1 - o0), 1.0f);
        }
        uint4 st;
        st.x = f2tf((a0.x + a1.x + a2.x + a3.x) * inv);
        st.y = f2tf((a0.y + a1.y + a2.y + a3.y) * inv);
        st.z = f2tf((a0.z + a1.z + a2.z + a3.z) * inv);
        st.w = f2tf((a0.w + a1.w + a2.w + a3.w) * inv);
        ((uint4*)(sA + rl * SA_STRIDE))[lane] = st;
    }

    // ---------- Phase B: tf32 mma over K=256 in 4 chunks of 64 ---------------
    int rowBlk = (w >> 1) * 16;
    int colBlk = (w & 1) * 64;
    float acc[8][4];
#pragma unroll
    for (int j = 0; j < 8; j++)
#pragma unroll
        for (int d = 0; d < 4; d++) acc[j][d] = 0.f;

    for (int kt = 0; kt < 4; kt++) {
        __syncthreads();
#pragma unroll
        for (int i = 0; i < 8; i++) {
            int idx = tid + 256 * i;      // 0..2047
            int c   = idx >> 4;           // 0..127
            int kl4 = idx & 15;           // 0..15
            *(uint4*)(sW + c * SW_STRIDE + kl4 * 4) =
                *(const uint4*)(Wt + c * 256 + kt * 64 + kl4 * 4);
        }
        __syncthreads();
#pragma unroll
        for (int ks = 0; ks < 8; ks++) {
            int kkA = kt * 64 + ks * 8;
            int kkW = ks * 8;
            unsigned a0 = sA[(rowBlk + g) * SA_STRIDE + kkA + t];
            unsigned a1 = sA[(rowBlk + g + 8) * SA_STRIDE + kkA + t];
            unsigned a2 = sA[(rowBlk + g) * SA_STRIDE + kkA + t + 4];
            unsigned a3 = sA[(rowBlk + g + 8) * SA_STRIDE + kkA + t + 4];
#pragma unroll
            for (int j = 0; j < 8; j++) {
                unsigned b0 = sW[(colBlk + j * 8 + g) * SW_STRIDE + kkW + t];
                unsigned b1 = sW[(colBlk + j * 8 + g) * SW_STRIDE + kkW + t + 4];
                asm volatile(
                    "mma.sync.aligned.m16n8k8.row.col.f32.tf32.tf32.f32 "
                    "{%0,%1,%2,%3}, {%4,%5,%6,%7}, {%8,%9}, {%0,%1,%2,%3};"
                    : "+f"(acc[j][0]), "+f"(acc[j][1]),
                      "+f"(acc[j][2]), "+f"(acc[j][3])
                    : "r"(a0), "r"(a1), "r"(a2), "r"(a3), "r"(b0), "r"(b1));
            }
        }
    }

    // ---------- epilogue -----------------------------------------------------
    if (!FUSE_FC) {
#pragma unroll
        for (int j = 0; j < 8; j++) {
            int col = colBlk + j * 8 + 2 * t;
            float bc0 = sBias[col], bc1 = sBias[col + 1];
            int row0 = rowBase + rowBlk + g;
            int row1 = row0 + 8;
            if (row0 < n) {
                float2 o;
                o.x = fmaxf(acc[j][0] + bc0, 0.f);
                o.y = fmaxf(acc[j][1] + bc1, 0.f);
                *(float2*)(out + (long)row0 * F + col) = o;
            }
            if (row1 < n) {
                float2 o;
                o.x = fmaxf(acc[j][2] + bc0, 0.f);
                o.y = fmaxf(acc[j][3] + bc1, 0.f);
                *(float2*)(out + (long)row1 * F + col) = o;
            }
        }
    } else {
        float* sH = (float*)sA;
        __syncthreads();
#pragma unroll
        for (int j = 0; j < 8; j++) {
            int col = colBlk + j * 8 + 2 * t;
            float bc0 = sBias[col], bc1 = sBias[col + 1];
            int r0 = rowBlk + g;
            float2 h0, h1;
            h0.x = fmaxf(acc[j][0] + bc0, 0.f);
            h0.y = fmaxf(acc[j][1] + bc1, 0.f);
            h1.x = fmaxf(acc[j][2] + bc0, 0.f);
            h1.y = fmaxf(acc[j][3] + bc1, 0.f);
            *(float2*)(sH + r0 * SA_STRIDE + col) = h0;
            *(float2*)(sH + (r0 + 8) * SA_STRIDE + col) = h1;
        }
        __syncthreads();
        for (int r = 0; r < 8; r++) {
            int rl = w * 8 + r;
            int row = rowBase + rl;
            const float* hr = sH + rl * SA_STRIDE + lane * 4;
            float h0 = hr[0], h1 = hr[1], h2 = hr[2], h3 = hr[3];
            int c0 = lane * 4;
            float p0 = h0 * sFc[(c0 + 0) * 2 + 0] + h1 * sFc[(c0 + 1) * 2 + 0]
                     + h2 * sFc[(c0 + 2) * 2 + 0] + h3 * sFc[(c0 + 3) * 2 + 0];
            float p1 = h0 * sFc[(c0 + 0) * 2 + 1] + h1 * sFc[(c0 + 1) * 2 + 1]
                     + h2 * sFc[(c0 + 2) * 2 + 1] + h3 * sFc[(c0 + 3) * 2 + 1];
#pragma unroll
            for (int d = 16; d > 0; d >>= 1) {
                p0 += __shfl_xor_sync(0xFFFFFFFFu, p0, d);
                p1 += __shfl_xor_sync(0xFFFFFFFFu, p1, d);
            }
            if (lane == 0 && row < n) {
                float2 o;
                o.x = p0 + __ldg(&bfc[0]);
                o.y = p1 + __ldg(&bfc[1]);
                ((float2*)out)[row] = o;
            }
        }
    }
}

// -----------------------------------------------------------------------------
extern "C" void kernel_launch(void* const* d_in, const int* in_sizes, int n_in,
                              void* d_out, int out_size)
{
    const float* x    = (const float*)d_in[0];
    const void*  ei   = d_in[1];                 // int32 or int64, auto-detected
    const float* W1l  = (const float*)d_in[2];
    const float* W1r  = (const float*)d_in[3];
    const float* b1   = (const float*)d_in[4];
    const float* W2l  = (const float*)d_in[5];
    const float* W2r  = (const float*)d_in[6];
    const float* b2   = (const float*)d_in[7];
    const float* Wfc  = (const float*)d_in[8];
    const float* bfc  = (const float*)d_in[9];
    float*       out  = (float*)d_out;

    int n  = in_sizes[0] / F;       // 50000
    int nE = in_sizes[1] / 2;       // 800000

    int *cnt, *off, *cur, *csr, *part;
    float *h1;
    unsigned *Wt1, *Wt2;
    cudaGetSymbolAddress((void**)&cnt,  g_cnt);
    cudaGetSymbolAddress((void**)&off,  g_off);
    cudaGetSymbolAddress((void**)&cur,  g_cur);
    cudaGetSymbolAddress((void**)&csr,  g_csr);
    cudaGetSymbolAddress((void**)&part, g_part);
    cudaGetSymbolAddress((void**)&h1,   g_h1);
    cudaGetSymbolAddress((void**)&Wt1,  g_Wt1);
    cudaGetSymbolAddress((void**)&Wt2,  g_Wt2);

    const int SMEM = SMEM_WORDS * 4;   // 102,912 bytes
    cudaFuncSetAttribute(sage_layer_kernel<0>,
                         cudaFuncAttributeMaxDynamicSharedMemorySize, SMEM);
    cudaFuncSetAttribute(sage_layer_kernel<1>,
                         cudaFuncAttributeMaxDynamicSharedMemorySize, SMEM);

    detect_kernel<<<1, 256>>>((const int*)ei);

    // ---- weight prep (both layers, one launch) ----
    wprep_kernel<<<256, 256>>>(W1l, W1r, W2l, W2r, Wt1, Wt2);

    // ---- CSR build (once, reused for both layers) ----
    int nb = (n + 1023) / 1024;                 // 49
    int nPair = (nE + 1) / 2;
    zero2_kernel<<<128, 256>>>(cnt, cur, (n + 3) / 4);
    count_kernel<<<(nPair + 255) / 256, 256>>>(ei, cnt, nE);
    scan1_kernel<<<nb, 1024>>>(cnt, off, part, n);
    scan3_kernel<<<nb, 1024>>>(off, part, n, nb);
    fill_kernel<<<(nPair + 255) / 256, 256>>>(ei, off, cur, csr, nE);

    int blocks = (n + 63) / 64;

    // ---- layer 1 (writes h1) ----
    sage_layer_kernel<0><<<blocks, 256, SMEM>>>(
        off, csr, x, Wt1, b1, (const float*)0, (const float*)0, h1, n);

    // ---- layer 2 + FC head fused (writes logits) ----
    sage_layer_kernel<1><<<blocks, 256, SMEM>>>(
        off, csr, h1, Wt2, b2, Wfc, bfc, out, n);
}